// round 4
// baseline (speedup 1.0000x reference)
#include <cuda_runtime.h>
#include <cuda_bf16.h>
#include <cstdint>

// ---------------------------------------------------------------------------
// QWenAttention: B=1, S=2048, H=2048, NH=16, HD=128
//   qkv = hidden @ w_qkv + b_qkv        [2048, 6144]
//   rope(q, k)
//   ctx = causal_softmax(q k^T / sqrt(128)) v   per head
//   out = ctx @ w_proj                  [2048, 2048]
// GEMMs: TF32 tensor cores (mma.sync m16n8k8), padded smem.
// Attention: SIMT fp32 flash.
// RoPE: cos/sin table precomputed in DOUBLE precision (immune to fast-math
// lowering of single-precision transcendentals, which degrades badly at
// |angle| ~ 2048 rad and is the prime suspect for the stable 0.672 rel_err).
// ---------------------------------------------------------------------------

#define S_LEN 2048
#define HID   2048
#define NHEAD 16
#define HDIM  128
#define QKV_N 6144

// Scratch (device globals: allocation-free per harness rules)
__device__ __align__(16) float g_qkv[S_LEN * QKV_N];   // 50.3 MB
__device__ __align__(16) float g_ctx[S_LEN * HID];     // 16.8 MB
__device__ __align__(16) float g_cos[S_LEN * 64];      // 0.5 MB
__device__ __align__(16) float g_sin[S_LEN * 64];      // 0.5 MB

// ---------------------------------------------------------------------------
// helpers
// ---------------------------------------------------------------------------
__device__ __forceinline__ uint32_t f2tf(float x) {
    uint32_t u;
    asm("cvt.rna.tf32.f32 %0, %1;" : "=r"(u) : "f"(x));
    return u;
}
__device__ __forceinline__ float4 tf4(float4 v) {
    v.x = __uint_as_float(f2tf(v.x));
    v.y = __uint_as_float(f2tf(v.y));
    v.z = __uint_as_float(f2tf(v.z));
    v.w = __uint_as_float(f2tf(v.w));
    return v;
}
__device__ __forceinline__ void mma_tf32(float* c, const uint32_t* a, const uint32_t* b) {
    asm volatile(
        "mma.sync.aligned.m16n8k8.row.col.f32.tf32.tf32.f32 "
        "{%0,%1,%2,%3}, {%4,%5,%6,%7}, {%8,%9}, {%0,%1,%2,%3};\n"
        : "+f"(c[0]), "+f"(c[1]), "+f"(c[2]), "+f"(c[3])
        : "r"(a[0]), "r"(a[1]), "r"(a[2]), "r"(a[3]), "r"(b[0]), "r"(b[1]));
}

// ---------------------------------------------------------------------------
// GEMM: C[M,N] = A[M,K] @ B[K,N] (+bias), row-major, TF32 mma.
// Block tile 128x128x32, 256 threads = 8 warps (4Mx2N), warp tile 32x64.
// Padded smem: fragment loads are full 32-bank permutations.
// ---------------------------------------------------------------------------
#define A_STRIDE 36
#define B_STRIDE 136

template <bool HAS_BIAS>
__global__ __launch_bounds__(256) void gemm_tf32_kernel(
    const float* __restrict__ A, const float* __restrict__ B,
    const float* __restrict__ bias, float* __restrict__ C,
    int M, int N, int K)
{
    __shared__ __align__(16) float As[128 * A_STRIDE];
    __shared__ __align__(16) float Bs[32 * B_STRIDE];

    const int tid  = threadIdx.x;
    const int warp = tid >> 5;
    const int lane = tid & 31;
    const int lr = lane >> 2;   // groupID 0..7
    const int lc = lane & 3;    // threadID_in_group 0..3
    const int wm = (warp >> 1) * 32;
    const int wn = (warp & 1) * 64;
    const int m0 = blockIdx.y * 128;
    const int n0 = blockIdx.x * 128;

    float acc[2][8][4];
#pragma unroll
    for (int i = 0; i < 2; i++)
#pragma unroll
        for (int j = 0; j < 8; j++)
#pragma unroll
            for (int c = 0; c < 4; c++) acc[i][j][c] = 0.f;

    for (int kb = 0; kb < K; kb += 32) {
        __syncthreads();
#pragma unroll
        for (int i = 0; i < 4; i++) {
            int m  = (tid >> 3) + i * 32;
            int k4 = tid & 7;
            float4 v = *(const float4*)(A + (size_t)(m0 + m) * K + kb + k4 * 4);
            *(float4*)(As + m * A_STRIDE + k4 * 4) = tf4(v);
        }
#pragma unroll
        for (int i = 0; i < 4; i++) {
            int k  = (tid >> 5) + i * 8;
            int n4 = tid & 31;
            float4 v = *(const float4*)(B + (size_t)(kb + k) * N + n0 + n4 * 4);
            *(float4*)(Bs + k * B_STRIDE + n4 * 4) = tf4(v);
        }
        __syncthreads();

#pragma unroll
        for (int kk = 0; kk < 32; kk += 8) {
            uint32_t a[2][4];
#pragma unroll
            for (int mf = 0; mf < 2; mf++) {
                int mb = wm + mf * 16;
                a[mf][0] = __float_as_uint(As[(mb + lr)     * A_STRIDE + kk + lc]);
                a[mf][1] = __float_as_uint(As[(mb + lr + 8) * A_STRIDE + kk + lc]);
                a[mf][2] = __float_as_uint(As[(mb + lr)     * A_STRIDE + kk + 4 + lc]);
                a[mf][3] = __float_as_uint(As[(mb + lr + 8) * A_STRIDE + kk + 4 + lc]);
            }
#pragma unroll
            for (int nf = 0; nf < 8; nf++) {
                uint32_t b[2];
                int n = wn + nf * 8 + lr;
                b[0] = __float_as_uint(Bs[(kk + lc)     * B_STRIDE + n]);
                b[1] = __float_as_uint(Bs[(kk + 4 + lc) * B_STRIDE + n]);
                mma_tf32(acc[0][nf], a[0], b);
                mma_tf32(acc[1][nf], a[1], b);
            }
        }
    }

#pragma unroll
    for (int mf = 0; mf < 2; mf++)
#pragma unroll
        for (int nf = 0; nf < 8; nf++)
#pragma unroll
            for (int c = 0; c < 4; c++) {
                int row = m0 + wm + mf * 16 + lr + ((c >> 1) << 3);
                int col = n0 + wn + nf * 8 + 2 * lc + (c & 1);
                float v = acc[mf][nf][c];
                if (HAS_BIAS) v += bias[col];
                C[(size_t)row * N + col] = v;
            }
}

// ---------------------------------------------------------------------------
// RoPE cos/sin table: DOUBLE precision pow/sincos (not altered by fast-math).
// Mimics ref: inv_freq fp32-rounded, angle = fp32(s * inv_freq), then
// accurately-rounded cos/sin of that fp32 angle.
// ---------------------------------------------------------------------------
__global__ void rope_table_kernel()
{
    int idx = blockIdx.x * blockDim.x + threadIdx.x;  // S*64
    if (idx >= S_LEN * 64) return;
    int i = idx & 63;
    int s = idx >> 6;
    double invf_d = pow(10000.0, -(double)(2 * i) / 128.0);
    float invf_f  = (float)invf_d;
    float ang_f   = (float)s * invf_f;      // fp32 product, matches ref
    double ds, dc;
    sincos((double)ang_f, &ds, &dc);
    g_cos[idx] = (float)dc;
    g_sin[idx] = (float)ds;
}

// ---------------------------------------------------------------------------
// RoPE apply (in-place on q,k inside g_qkv), table-driven transcription of
// q' = q * cos + rotate_half(q) * sin  with emb = [freqs, freqs].
// ---------------------------------------------------------------------------
__global__ void rope_apply_kernel(float* __restrict__ qkv)
{
    int idx = blockIdx.x * blockDim.x + threadIdx.x; // S*NH*64 threads
    int j = idx & 63;
    int h = (idx >> 6) & 15;
    int s = idx >> 10;
    if (s >= S_LEN) return;

    float c  = g_cos[s * 64 + j];
    float sn = g_sin[s * 64 + j];

    float* q = qkv + (size_t)s * QKV_N + h * HDIM + j;
    float* k = q + HID;
    float q1 = q[0], q2 = q[64];
    q[0]  = q1 * c - q2 * sn;   // first half: + (-x2)*sin
    q[64] = q2 * c + q1 * sn;   // second half: + x1*sin (same freq: emb concat)
    float k1 = k[0], k2 = k[64];
    k[0]  = k1 * c - k2 * sn;
    k[64] = k2 * c + k1 * sn;
}

// ---------------------------------------------------------------------------
// SIMT fp32 flash attention, causal.
// Block = 32 queries x 1 head, 256 threads: 8 threads per query row; thread g
// owns dims d = c*32 + g*4 + (0..3). Butterfly-shfl dot reduction; softmax
// state replicated bit-identically across the 8-thread group.
// ---------------------------------------------------------------------------
__global__ __launch_bounds__(256) void flash_simt_kernel(
    const float* __restrict__ qkv, float* __restrict__ ctx)
{
    __shared__ __align__(16) float Ks[32][128];
    __shared__ __align__(16) float Vs[32][128];

    const int tid = threadIdx.x;
    const int h   = blockIdx.y;
    const int qt  = (int)gridDim.x - 1 - blockIdx.x;  // heavy tiles first
    const int q0  = qt * 32;
    const int qg  = q0 + (tid >> 3);      // global query row
    const int g   = tid & 7;              // dim-group within row
    const float scale = 0.08838834764831845f;  // 1/sqrt(128)

    float4 Q[4];
    {
        const float* Qp = qkv + (size_t)qg * QKV_N + h * HDIM + g * 4;
#pragma unroll
        for (int c = 0; c < 4; c++) {
            float4 v = *(const float4*)(Qp + c * 32);
            v.x *= scale; v.y *= scale; v.z *= scale; v.w *= scale;
            Q[c] = v;
        }
    }

    float4 O[4];
#pragma unroll
    for (int c = 0; c < 4; c++) O[c] = make_float4(0.f, 0.f, 0.f, 0.f);
    float m = -1e30f, l = 0.f;

    const int ntiles = qt + 1;
    for (int j = 0; j < ntiles; j++) {
        __syncthreads();
        for (int it = tid; it < 32 * 32; it += 256) {
            int key = it >> 5;
            int c4  = it & 31;
            const float* Kg = qkv + (size_t)(j * 32 + key) * QKV_N + HID + h * HDIM + c4 * 4;
            *(float4*)&Ks[key][c4 * 4] = *(const float4*)Kg;
            *(float4*)&Vs[key][c4 * 4] = *(const float4*)(Kg + HID);
        }
        __syncthreads();

        float s[32];
#pragma unroll
        for (int k = 0; k < 32; k++) {
            float p = 0.f;
#pragma unroll
            for (int c = 0; c < 4; c++) {
                float4 kv = *(const float4*)&Ks[k][c * 32 + g * 4];
                p += Q[c].x * kv.x + Q[c].y * kv.y + Q[c].z * kv.z + Q[c].w * kv.w;
            }
            p += __shfl_xor_sync(0xffffffffu, p, 1);
            p += __shfl_xor_sync(0xffffffffu, p, 2);
            p += __shfl_xor_sync(0xffffffffu, p, 4);
            s[k] = (j * 32 + k > qg) ? -1e30f : p;
        }

        float tmax = -1e30f;
#pragma unroll
        for (int k = 0; k < 32; k++) tmax = fmaxf(tmax, s[k]);
        float mn = fmaxf(m, tmax);
        float a = __expf(m - mn);
        l *= a;
#pragma unroll
        for (int c = 0; c < 4; c++) {
            O[c].x *= a; O[c].y *= a; O[c].z *= a; O[c].w *= a;
        }
#pragma unroll
        for (int k = 0; k < 32; k++) {
            float p = __expf(s[k] - mn);
            l += p;
#pragma unroll
            for (int c = 0; c < 4; c++) {
                float4 vv = *(const float4*)&Vs[k][c * 32 + g * 4];
                O[c].x += p * vv.x; O[c].y += p * vv.y;
                O[c].z += p * vv.z; O[c].w += p * vv.w;
            }
        }
        m = mn;
    }

    float r = 1.f / l;
    float* Op = ctx + (size_t)qg * HID + h * HDIM + g * 4;
#pragma unroll
    for (int c = 0; c < 4; c++) {
        float4 v = O[c];
        v.x *= r; v.y *= r; v.z *= r; v.w *= r;
        *(float4*)(Op + c * 32) = v;
    }
}

// ---------------------------------------------------------------------------
// launcher
// ---------------------------------------------------------------------------
extern "C" void kernel_launch(void* const* d_in, const int* in_sizes, int n_in,
                              void* d_out, int out_size)
{
    const float* hidden = nullptr;
    const float* w_qkv  = nullptr;
    const float* b_qkv  = nullptr;
    const float* w_proj = nullptr;
    for (int i = 0; i < n_in; i++) {
        long sz = in_sizes[i];
        const float* p = (const float*)d_in[i];
        if (sz == (long)HID * QKV_N)      w_qkv = p;            // 12.58M
        else if (sz == (long)QKV_N)       b_qkv = p;            // 6144
        else {                                                   // 4.19M x2
            if (!hidden) hidden = p; else w_proj = p;            // dict order
        }
    }
    float* out = (float*)d_out;

    float* qkv = nullptr;
    float* ctx = nullptr;
    cudaGetSymbolAddress((void**)&qkv, g_qkv);
    cudaGetSymbolAddress((void**)&ctx, g_ctx);

    // 0) rope table (double-precision transcendentals; overlapped w/ nothing,
    //    but tiny: 131072 threads)
    rope_table_kernel<<<(S_LEN * 64) / 256, 256>>>();
    // 1) qkv = hidden @ w_qkv + b
    gemm_tf32_kernel<true><<<dim3(QKV_N / 128, S_LEN / 128), 256>>>(
        hidden, w_qkv, b_qkv, qkv, S_LEN, QKV_N, HID);
    // 2) rope in-place on q,k
    rope_apply_kernel<<<(S_LEN * NHEAD * 64) / 256, 256>>>(qkv);
    // 3) attention (SIMT fp32 flash)
    flash_simt_kernel<<<dim3(S_LEN / 32, NHEAD), 256>>>(qkv, ctx);
    // 4) out = ctx @ w_proj
    gemm_tf32_kernel<false><<<dim3(HID / 128, S_LEN / 128), 256>>>(
        ctx, w_proj, nullptr, out, S_LEN, HID, HID);
}

// round 6
// speedup vs baseline: 2.4432x; 2.4432x over previous
#include <cuda_runtime.h>
#include <cuda_bf16.h>
#include <cstdint>

// ---------------------------------------------------------------------------
// QWenAttention: B=1, S=2048, H=2048, NH=16, HD=128
//   qkv = hidden @ w_qkv + b_qkv        [2048, 6144]
//   rope(q, k)
//   ctx = causal_softmax(q k^T / sqrt(128)) v   per head
//   out = ctx @ w_proj                  [2048, 2048]
// GEMMs: TF32 mma, cp.async 2-stage pipeline (dynamic smem), operands
// pre-converted to TF32. Attention: TF32 mma flash. RoPE: fp64 table.
// ---------------------------------------------------------------------------

#define S_LEN 2048
#define HID   2048
#define NHEAD 16
#define HDIM  128
#define QKV_N 6144

// Scratch (device globals: allocation-free per harness rules)
__device__ __align__(16) float g_qkv[S_LEN * QKV_N];    // 50.3 MB (fp32)
__device__ __align__(16) float g_ctx[S_LEN * HID];      // 16.8 MB (tf32 bits)
__device__ __align__(16) float g_cos[S_LEN * 64];
__device__ __align__(16) float g_sin[S_LEN * 64];
__device__ __align__(16) float g_hid_tf[S_LEN * HID];   // 16.8 MB
__device__ __align__(16) float g_w1_tf[HID * QKV_N];    // 50.3 MB
__device__ __align__(16) float g_w2_tf[HID * HID];      // 16.8 MB

// ---------------------------------------------------------------------------
// helpers
// ---------------------------------------------------------------------------
__device__ __forceinline__ uint32_t f2tf(float x) {
    uint32_t u;
    asm("cvt.rna.tf32.f32 %0, %1;" : "=r"(u) : "f"(x));
    return u;
}
__device__ __forceinline__ float4 tf4(float4 v) {
    v.x = __uint_as_float(f2tf(v.x));
    v.y = __uint_as_float(f2tf(v.y));
    v.z = __uint_as_float(f2tf(v.z));
    v.w = __uint_as_float(f2tf(v.w));
    return v;
}
__device__ __forceinline__ void mma_tf32(float* c, const uint32_t* a, const uint32_t* b) {
    asm volatile(
        "mma.sync.aligned.m16n8k8.row.col.f32.tf32.tf32.f32 "
        "{%0,%1,%2,%3}, {%4,%5,%6,%7}, {%8,%9}, {%0,%1,%2,%3};\n"
        : "+f"(c[0]), "+f"(c[1]), "+f"(c[2]), "+f"(c[3])
        : "r"(a[0]), "r"(a[1]), "r"(a[2]), "r"(a[3]), "r"(b[0]), "r"(b[1]));
}
__device__ __forceinline__ void cpa16(float* s, const float* g) {
    uint32_t sa = (uint32_t)__cvta_generic_to_shared(s);
    asm volatile("cp.async.cg.shared.global [%0], [%1], 16;\n" :: "r"(sa), "l"(g));
}

// ---------------------------------------------------------------------------
// TF32 pre-conversion (elementwise rna)
// ---------------------------------------------------------------------------
__global__ void tf32_convert_kernel(const float* __restrict__ in,
                                    float* __restrict__ out, int n4)
{
    int i = blockIdx.x * blockDim.x + threadIdx.x;
    if (i < n4) ((float4*)out)[i] = tf4(((const float4*)in)[i]);
}

// ---------------------------------------------------------------------------
// GEMM: C[M,N] = A[M,K] @ B[K,N] (+bias). A,B already tf32-rounded.
// Block tile 128x128x32, 256 threads = 8 warps (4Mx2N), warp tile 32x64.
// cp.async 2-stage pipeline; DYNAMIC smem (71,680 B > 48 KB static cap);
// padded strides give full 32-bank permutations on fragment loads.
// ---------------------------------------------------------------------------
#define A_STRIDE 36
#define B_STRIDE 136
#define GEMM_SMEM_BYTES ((2 * 128 * A_STRIDE + 2 * 32 * B_STRIDE) * 4)  // 71680

template <bool HAS_BIAS>
__global__ __launch_bounds__(256, 2) void gemm_tf32_async(
    const float* __restrict__ A, const float* __restrict__ B,
    const float* __restrict__ bias, float* __restrict__ C,
    int M, int N, int K)
{
    extern __shared__ __align__(16) float smem[];
    float* As[2] = { smem, smem + 128 * A_STRIDE };
    float* Bs[2] = { smem + 2 * 128 * A_STRIDE,
                     smem + 2 * 128 * A_STRIDE + 32 * B_STRIDE };

    const int tid  = threadIdx.x;
    const int warp = tid >> 5;
    const int lane = tid & 31;
    const int lr = lane >> 2;
    const int lc = lane & 3;
    const int wm = (warp >> 1) * 32;
    const int wn = (warp & 1) * 64;
    const int m0 = blockIdx.y * 128;
    const int n0 = blockIdx.x * 128;

    float acc[2][8][4];
#pragma unroll
    for (int i = 0; i < 2; i++)
#pragma unroll
        for (int j = 0; j < 8; j++)
#pragma unroll
            for (int c = 0; c < 4; c++) acc[i][j][c] = 0.f;

    const int am = (tid >> 3), ak = (tid & 7) * 4;
    const int bk = (tid >> 5), bn = (tid & 31) * 4;

    auto load_stage = [&](int st, int kb) {
#pragma unroll
        for (int i = 0; i < 4; i++)
            cpa16(&As[st][(am + i * 32) * A_STRIDE + ak],
                  A + (size_t)(m0 + am + i * 32) * K + kb + ak);
#pragma unroll
        for (int i = 0; i < 4; i++)
            cpa16(&Bs[st][(bk + i * 8) * B_STRIDE + bn],
                  B + (size_t)(kb + bk + i * 8) * N + n0 + bn);
        asm volatile("cp.async.commit_group;\n" ::);
    };

    const int nk = K / 32;
    load_stage(0, 0);

    for (int t = 0; t < nk; t++) {
        if (t + 1 < nk) {
            load_stage((t + 1) & 1, (t + 1) * 32);
            asm volatile("cp.async.wait_group 1;\n" ::);
        } else {
            asm volatile("cp.async.wait_group 0;\n" ::);
        }
        __syncthreads();
        const float* Asm = As[t & 1];
        const float* Bsm = Bs[t & 1];

#pragma unroll
        for (int kk = 0; kk < 32; kk += 8) {
            uint32_t a[2][4];
#pragma unroll
            for (int mf = 0; mf < 2; mf++) {
                int mb = wm + mf * 16;
                a[mf][0] = __float_as_uint(Asm[(mb + lr)     * A_STRIDE + kk + lc]);
                a[mf][1] = __float_as_uint(Asm[(mb + lr + 8) * A_STRIDE + kk + lc]);
                a[mf][2] = __float_as_uint(Asm[(mb + lr)     * A_STRIDE + kk + 4 + lc]);
                a[mf][3] = __float_as_uint(Asm[(mb + lr + 8) * A_STRIDE + kk + 4 + lc]);
            }
#pragma unroll
            for (int nf = 0; nf < 8; nf++) {
                uint32_t b[2];
                int n = wn + nf * 8 + lr;
                b[0] = __float_as_uint(Bsm[(kk + lc)     * B_STRIDE + n]);
                b[1] = __float_as_uint(Bsm[(kk + 4 + lc) * B_STRIDE + n]);
                mma_tf32(acc[0][nf], a[0], b);
                mma_tf32(acc[1][nf], a[1], b);
            }
        }
        __syncthreads();
    }

#pragma unroll
    for (int mf = 0; mf < 2; mf++)
#pragma unroll
        for (int nf = 0; nf < 8; nf++)
#pragma unroll
            for (int c = 0; c < 4; c++) {
                int row = m0 + wm + mf * 16 + lr + ((c >> 1) << 3);
                int col = n0 + wn + nf * 8 + 2 * lc + (c & 1);
                float v = acc[mf][nf][c];
                if (HAS_BIAS) v += bias[col];
                C[(size_t)row * N + col] = v;
            }
}

// ---------------------------------------------------------------------------
// RoPE cos/sin table: double-precision pow/sincos (fast-math-proof).
// ---------------------------------------------------------------------------
__global__ void rope_table_kernel()
{
    int idx = blockIdx.x * blockDim.x + threadIdx.x;  // S*64
    if (idx >= S_LEN * 64) return;
    int i = idx & 63;
    int s = idx >> 6;
    double invf_d = pow(10000.0, -(double)(2 * i) / 128.0);
    float invf_f  = (float)invf_d;
    float ang_f   = (float)s * invf_f;
    double ds, dc;
    sincos((double)ang_f, &ds, &dc);
    g_cos[idx] = (float)dc;
    g_sin[idx] = (float)ds;
}

// ---------------------------------------------------------------------------
// RoPE apply (in-place on q,k inside g_qkv)
// ---------------------------------------------------------------------------
__global__ void rope_apply_kernel(float* __restrict__ qkv)
{
    int idx = blockIdx.x * blockDim.x + threadIdx.x;
    int j = idx & 63;
    int h = (idx >> 6) & 15;
    int s = idx >> 10;
    if (s >= S_LEN) return;

    float c  = g_cos[s * 64 + j];
    float sn = g_sin[s * 64 + j];

    float* q = qkv + (size_t)s * QKV_N + h * HDIM + j;
    float* k = q + HID;
    float q1 = q[0], q2 = q[64];
    q[0]  = q1 * c - q2 * sn;
    q[64] = q2 * c + q1 * sn;
    float k1 = k[0], k2 = k[64];
    k[0]  = k1 * c - k2 * sn;
    k[64] = k2 * c + k1 * sn;
}

// ---------------------------------------------------------------------------
// TF32 mma flash attention, causal. Block = 128 queries x 1 head, 8 warps
// (16 rows each). 32-key tiles. Q pre-scaled, held as A-fragments in regs.
// Smem: Ks (stride 132) unioned with per-warp P (stride 36), Vs (stride 136).
// Extra barrier protects the Ks/P alias. ctx written tf32-rounded.
// ---------------------------------------------------------------------------
#define KS_STRIDE 132
#define VS_STRIDE 136
#define PS_STRIDE 36

__global__ __launch_bounds__(256) void flash_mma_kernel(
    const float* __restrict__ qkv, float* __restrict__ ctx)
{
    __shared__ __align__(16) float KP[8 * 16 * PS_STRIDE];  // 4608 >= 32*132
    __shared__ __align__(16) float Vs[32 * VS_STRIDE];

    const int tid  = threadIdx.x;
    const int warp = tid >> 5;
    const int lane = tid & 31;
    const int lr = lane >> 2;
    const int lc = lane & 3;
    const int qt = 15 - blockIdx.x;        // heavy tiles first
    const int h  = blockIdx.y;
    const int q0 = qt * 128;
    const float scale = 0.08838834764831845f;  // 1/sqrt(128)

    uint32_t qa[16][4];
    {
        const float* Qb = qkv + (size_t)(q0 + warp * 16) * QKV_N + h * HDIM;
#pragma unroll
        for (int ks = 0; ks < 16; ks++) {
            qa[ks][0] = f2tf(scale * Qb[(size_t)lr       * QKV_N + ks * 8 + lc]);
            qa[ks][1] = f2tf(scale * Qb[(size_t)(lr + 8) * QKV_N + ks * 8 + lc]);
            qa[ks][2] = f2tf(scale * Qb[(size_t)lr       * QKV_N + ks * 8 + 4 + lc]);
            qa[ks][3] = f2tf(scale * Qb[(size_t)(lr + 8) * QKV_N + ks * 8 + 4 + lc]);
        }
    }

    float o[16][4];
#pragma unroll
    for (int i = 0; i < 16; i++)
#pragma unroll
        for (int c = 0; c < 4; c++) o[i][c] = 0.f;
    float mA = -1e30f, mB = -1e30f, lA = 0.f, lB = 0.f;

    const int rowA = q0 + warp * 16 + lr;
    const int rowB = rowA + 8;
    const int rowMaxWarp = q0 + warp * 16 + 15;
    const int ntiles = qt * 4 + 4;

    for (int j = 0; j < ntiles; j++) {
        __syncthreads();
#pragma unroll
        for (int i = 0; i < 4; i++) {
            int key = (tid >> 5) + i * 8;
            int d4  = (tid & 31) * 4;
            const float* Kg = qkv + (size_t)(j * 32 + key) * QKV_N + HID + h * HDIM + d4;
            *(float4*)&KP[key * KS_STRIDE + d4] = tf4(*(const float4*)Kg);
            *(float4*)&Vs[key * VS_STRIDE + d4] = tf4(*(const float4*)(Kg + HID));
        }
        __syncthreads();

        const bool active = (j * 32 <= rowMaxWarp);
        float s[4][4];
        if (active) {
#pragma unroll
            for (int nf = 0; nf < 4; nf++)
#pragma unroll
                for (int c = 0; c < 4; c++) s[nf][c] = 0.f;
#pragma unroll
            for (int ks = 0; ks < 16; ks++) {
#pragma unroll
                for (int nf = 0; nf < 4; nf++) {
                    uint32_t b[2];
                    int key = nf * 8 + lr;
                    b[0] = __float_as_uint(KP[key * KS_STRIDE + ks * 8 + lc]);
                    b[1] = __float_as_uint(KP[key * KS_STRIDE + ks * 8 + 4 + lc]);
                    mma_tf32(s[nf], qa[ks], b);
                }
            }
        }
        __syncthreads();   // all Ks reads done before P writes (alias)

        if (active) {
#pragma unroll
            for (int nf = 0; nf < 4; nf++) {
                int col0 = j * 32 + nf * 8 + 2 * lc;
                if (col0     > rowA) s[nf][0] = -1e30f;
                if (col0 + 1 > rowA) s[nf][1] = -1e30f;
                if (col0     > rowB) s[nf][2] = -1e30f;
                if (col0 + 1 > rowB) s[nf][3] = -1e30f;
            }

            float tA = -1e30f, tB = -1e30f;
#pragma unroll
            for (int nf = 0; nf < 4; nf++) {
                tA = fmaxf(tA, fmaxf(s[nf][0], s[nf][1]));
                tB = fmaxf(tB, fmaxf(s[nf][2], s[nf][3]));
            }
            tA = fmaxf(tA, __shfl_xor_sync(0xffffffffu, tA, 1));
            tA = fmaxf(tA, __shfl_xor_sync(0xffffffffu, tA, 2));
            tB = fmaxf(tB, __shfl_xor_sync(0xffffffffu, tB, 1));
            tB = fmaxf(tB, __shfl_xor_sync(0xffffffffu, tB, 2));

            float mAn = fmaxf(mA, tA), mBn = fmaxf(mB, tB);
            float aA = __expf(mA - mAn), aB = __expf(mB - mBn);
            float sA = 0.f, sB = 0.f;
#pragma unroll
            for (int nf = 0; nf < 4; nf++) {
                s[nf][0] = __expf(s[nf][0] - mAn);
                s[nf][1] = __expf(s[nf][1] - mAn);
                s[nf][2] = __expf(s[nf][2] - mBn);
                s[nf][3] = __expf(s[nf][3] - mBn);
                sA += s[nf][0] + s[nf][1];
                sB += s[nf][2] + s[nf][3];
            }
            sA += __shfl_xor_sync(0xffffffffu, sA, 1);
            sA += __shfl_xor_sync(0xffffffffu, sA, 2);
            sB += __shfl_xor_sync(0xffffffffu, sB, 1);
            sB += __shfl_xor_sync(0xffffffffu, sB, 2);
            lA = lA * aA + sA;
            lB = lB * aB + sB;
            mA = mAn; mB = mBn;
#pragma unroll
            for (int nf = 0; nf < 16; nf++) {
                o[nf][0] *= aA; o[nf][1] *= aA;
                o[nf][2] *= aB; o[nf][3] *= aB;
            }

            float* P = KP + warp * 16 * PS_STRIDE;
#pragma unroll
            for (int nf = 0; nf < 4; nf++)
#pragma unroll
                for (int c = 0; c < 4; c++) {
                    int r  = lr + ((c >> 1) << 3);
                    int kc = nf * 8 + 2 * lc + (c & 1);
                    P[r * PS_STRIDE + kc] = __uint_as_float(f2tf(s[nf][c]));
                }
            __syncwarp();

#pragma unroll
            for (int kk = 0; kk < 4; kk++) {
                uint32_t pa[4];
                pa[0] = __float_as_uint(P[lr       * PS_STRIDE + kk * 8 + lc]);
                pa[1] = __float_as_uint(P[(lr + 8) * PS_STRIDE + kk * 8 + lc]);
                pa[2] = __float_as_uint(P[lr       * PS_STRIDE + kk * 8 + 4 + lc]);
                pa[3] = __float_as_uint(P[(lr + 8) * PS_STRIDE + kk * 8 + 4 + lc]);
#pragma unroll
                for (int nf = 0; nf < 16; nf++) {
                    uint32_t b[2];
                    int hd = nf * 8 + lr;
                    b[0] = __float_as_uint(Vs[(kk * 8 + lc)     * VS_STRIDE + hd]);
                    b[1] = __float_as_uint(Vs[(kk * 8 + 4 + lc) * VS_STRIDE + hd]);
                    mma_tf32(o[nf], pa, b);
                }
            }
        }
    }

    float rA = 1.f / lA, rB = 1.f / lB;
#pragma unroll
    for (int nf = 0; nf < 16; nf++) {
        int col = h * HDIM + nf * 8 + 2 * lc;
        ctx[(size_t)rowA * HID + col]     = __uint_as_float(f2tf(o[nf][0] * rA));
        ctx[(size_t)rowA * HID + col + 1] = __uint_as_float(f2tf(o[nf][1] * rA));
        ctx[(size_t)rowB * HID + col]     = __uint_as_float(f2tf(o[nf][2] * rB));
        ctx[(size_t)rowB * HID + col + 1] = __uint_as_float(f2tf(o[nf][3] * rB));
    }
}

// ---------------------------------------------------------------------------
// launcher
// ---------------------------------------------------------------------------
extern "C" void kernel_launch(void* const* d_in, const int* in_sizes, int n_in,
                              void* d_out, int out_size)
{
    const float* hidden = nullptr;
    const float* w_qkv  = nullptr;
    const float* b_qkv  = nullptr;
    const float* w_proj = nullptr;
    for (int i = 0; i < n_in; i++) {
        long sz = in_sizes[i];
        const float* p = (const float*)d_in[i];
        if (sz == (long)HID * QKV_N)      w_qkv = p;
        else if (sz == (long)QKV_N)       b_qkv = p;
        else {
            if (!hidden) hidden = p; else w_proj = p;
        }
    }
    float* out = (float*)d_out;

    float *qkv, *ctx, *hid_tf, *w1_tf, *w2_tf;
    cudaGetSymbolAddress((void**)&qkv,    g_qkv);
    cudaGetSymbolAddress((void**)&ctx,    g_ctx);
    cudaGetSymbolAddress((void**)&hid_tf, g_hid_tf);
    cudaGetSymbolAddress((void**)&w1_tf,  g_w1_tf);
    cudaGetSymbolAddress((void**)&w2_tf,  g_w2_tf);

    // raise dynamic smem cap for the GEMMs (host-side attribute, idempotent)
    cudaFuncSetAttribute(gemm_tf32_async<true>,
                         cudaFuncAttributeMaxDynamicSharedMemorySize,
                         GEMM_SMEM_BYTES);
    cudaFuncSetAttribute(gemm_tf32_async<false>,
                         cudaFuncAttributeMaxDynamicSharedMemorySize,
                         GEMM_SMEM_BYTES);

    // 0) rope table + tf32 pre-conversions
    rope_table_kernel<<<(S_LEN * 64) / 256, 256>>>();
    tf32_convert_kernel<<<(S_LEN * HID / 4) / 256, 256>>>(hidden, hid_tf, S_LEN * HID / 4);
    tf32_convert_kernel<<<(HID * QKV_N / 4) / 256, 256>>>(w_qkv, w1_tf, HID * QKV_N / 4);
    tf32_convert_kernel<<<(HID * HID / 4) / 256, 256>>>(w_proj, w2_tf, HID * HID / 4);

    // 1) qkv = hidden @ w_qkv + b
    gemm_tf32_async<true><<<dim3(QKV_N / 128, S_LEN / 128), 256, GEMM_SMEM_BYTES>>>(
        hid_tf, w1_tf, b_qkv, qkv, S_LEN, QKV_N, HID);
    // 2) rope in-place on q,k
    rope_apply_kernel<<<(S_LEN * NHEAD * 64) / 256, 256>>>(qkv);
    // 3) attention (tf32 mma flash)
    flash_mma_kernel<<<dim3(S_LEN / 128, NHEAD), 256>>>(qkv, ctx);
    // 4) out = ctx @ w_proj
    gemm_tf32_async<false><<<dim3(HID / 128, S_LEN / 128), 256, GEMM_SMEM_BYTES>>>(
        ctx, w2_tf, nullptr, out, S_LEN, HID, HID);
}

// round 9
// speedup vs baseline: 3.1208x; 1.2774x over previous
#include <cuda_runtime.h>
#include <cuda_fp16.h>
#include <cstdint>

// ---------------------------------------------------------------------------
// QWenAttention: B=1, S=2048, H=2048, NH=16, HD=128
//   qkv = hidden @ w_qkv + b_qkv        [2048, 6144]
//   rope(q, k)
//   ctx = causal_softmax(q k^T / sqrt(128)) v   per head
//   out = ctx @ w_proj                  [2048, 2048]
// All matmuls: fp16 mma.sync m16n8k16 (fp32 accum) — fp16 has the same
// 10-bit mantissa as TF32 but 2x the legacy-path rate (tcgen05 unavailable:
// harness targets plain sm_100). RoPE: fp64 cos/sin table (fast-math-proof).
// ---------------------------------------------------------------------------

#define S_LEN 2048
#define HID   2048
#define NHEAD 16
#define HDIM  128
#define QKV_N 6144

// Scratch (device globals: allocation-free per harness rules)
__device__ __align__(16) __half g_qkv_h[S_LEN * QKV_N];   // 25.2 MB
__device__ __align__(16) __half g_ctx_h[S_LEN * HID];     // 8.4 MB
__device__ __align__(16) __half g_hid_h[S_LEN * HID];     // 8.4 MB
__device__ __align__(16) __half g_w1t_h[QKV_N * HID];     // 25.2 MB [N,K]
__device__ __align__(16) __half g_w2t_h[HID * HID];       // 8.4 MB  [N,K]
__device__ __align__(16) float  g_cos[S_LEN * 64];
__device__ __align__(16) float  g_sin[S_LEN * 64];

// ---------------------------------------------------------------------------
// helpers
// ---------------------------------------------------------------------------
__device__ __forceinline__ void mma_fp16(float* c, const uint32_t* a, const uint32_t* b) {
    asm volatile(
        "mma.sync.aligned.m16n8k16.row.col.f32.f16.f16.f32 "
        "{%0,%1,%2,%3}, {%4,%5,%6,%7}, {%8,%9}, {%0,%1,%2,%3};\n"
        : "+f"(c[0]), "+f"(c[1]), "+f"(c[2]), "+f"(c[3])
        : "r"(a[0]), "r"(a[1]), "r"(a[2]), "r"(a[3]), "r"(b[0]), "r"(b[1]));
}
__device__ __forceinline__ void cpa16u(uint32_t s, const void* g) {
    asm volatile("cp.async.cg.shared.global [%0], [%1], 16;\n" :: "r"(s), "l"(g));
}
__device__ __forceinline__ uint32_t smem_u32(const void* p) {
    return (uint32_t)__cvta_generic_to_shared(p);
}
__device__ __forceinline__ uint32_t pack_h2(float lo, float hi) {
    __half2 h = __floats2half2_rn(lo, hi);
    return *(uint32_t*)&h;
}

// ---------------------------------------------------------------------------
// fp16 conversion / transpose prep
// ---------------------------------------------------------------------------
__global__ void convert_half_kernel(const float* __restrict__ in,
                                    __half* __restrict__ out, int n4)
{
    int i = blockIdx.x * blockDim.x + threadIdx.x;
    if (i >= n4) return;
    float4 v = ((const float4*)in)[i];
    ((__half2*)out)[i * 2]     = __floats2half2_rn(v.x, v.y);
    ((__half2*)out)[i * 2 + 1] = __floats2half2_rn(v.z, v.w);
}

// out[c][r] = half(in[r][c]); in: R x C fp32
__global__ void transpose_half_kernel(const float* __restrict__ in,
                                      __half* __restrict__ out, int R, int C)
{
    __shared__ float tile[32][33];
    int c0 = blockIdx.x * 32, r0 = blockIdx.y * 32;
    int tx = threadIdx.x, ty = threadIdx.y;  // 32 x 8
#pragma unroll
    for (int i = 0; i < 32; i += 8)
        tile[ty + i][tx] = in[(size_t)(r0 + ty + i) * C + c0 + tx];
    __syncthreads();
#pragma unroll
    for (int i = 0; i < 32; i += 8)
        out[(size_t)(c0 + ty + i) * R + r0 + tx] = __float2half(tile[tx][ty + i]);
}

// ---------------------------------------------------------------------------
// fp16 GEMM: C[M,N] = A[M,K] @ Bt^T (+bias)
//   A [M,K] half, Bt [N,K] half (K-contiguous), C half or float.
// Block 128x128x32, 256 threads = 8 warps (4Mx2N), warp tile 32x64.
// Smem word-based (uint32 = half2), stride 20 words (16 data + 4 pad):
// fragment loads hit banks 20*lr+lc (full 32-bank permutation).
// cp.async 2-stage pipeline; static smem 40KB.
// ---------------------------------------------------------------------------
#define GW 20   // gemm smem row stride in words

template <bool HAS_BIAS, typename OutT>
__global__ __launch_bounds__(256) void gemm_fp16_kernel(
    const __half* __restrict__ A, const __half* __restrict__ Bt,
    const float* __restrict__ bias, OutT* __restrict__ C,
    int M, int N, int K)
{
    __shared__ __align__(16) uint32_t As[2][128 * GW];
    __shared__ __align__(16) uint32_t Bs[2][128 * GW];

    const int tid  = threadIdx.x;
    const int warp = tid >> 5;
    const int lane = tid & 31;
    const int lr = lane >> 2;
    const int lc = lane & 3;
    const int wm = (warp >> 1) * 32;
    const int wn = (warp & 1) * 64;
    const int m0 = blockIdx.y * 128;
    const int n0 = blockIdx.x * 128;

    float acc[2][8][4];
#pragma unroll
    for (int i = 0; i < 2; i++)
#pragma unroll
        for (int j = 0; j < 8; j++)
#pragma unroll
            for (int c = 0; c < 4; c++) acc[i][j][c] = 0.f;

    const int row = tid >> 1;              // 128 rows, 2 threads/row
    const int jb  = (tid & 1) * 2;         // each thread: 2 x 16B chunks

    auto load_stage = [&](int st, int kb) {
#pragma unroll
        for (int j = 0; j < 2; j++) {
            int ch = jb + j;               // chunk 0..3 (8 halves each)
            cpa16u(smem_u32(&As[st][row * GW + ch * 4]),
                   A + (size_t)(m0 + row) * K + kb + ch * 8);
            cpa16u(smem_u32(&Bs[st][row * GW + ch * 4]),
                   Bt + (size_t)(n0 + row) * K + kb + ch * 8);
        }
        asm volatile("cp.async.commit_group;\n" ::);
    };

    const int nk = K / 32;
    load_stage(0, 0);

    for (int t = 0; t < nk; t++) {
        if (t + 1 < nk) {
            load_stage((t + 1) & 1, (t + 1) * 32);
            asm volatile("cp.async.wait_group 1;\n" ::);
        } else {
            asm volatile("cp.async.wait_group 0;\n" ::);
        }
        __syncthreads();
        const uint32_t* Asm = As[t & 1];
        const uint32_t* Bsm = Bs[t & 1];

#pragma unroll
        for (int step = 0; step < 2; step++) {   // 2 x k16
            uint32_t a[2][4];
#pragma unroll
            for (int mf = 0; mf < 2; mf++) {
                int mb = wm + mf * 16;
                a[mf][0] = Asm[(mb + lr)     * GW + step * 8 + lc];
                a[mf][1] = Asm[(mb + lr + 8) * GW + step * 8 + lc];
                a[mf][2] = Asm[(mb + lr)     * GW + step * 8 + lc + 4];
                a[mf][3] = Asm[(mb + lr + 8) * GW + step * 8 + lc + 4];
            }
#pragma unroll
            for (int nf = 0; nf < 8; nf++) {
                uint32_t b[2];
                int n = wn + nf * 8 + lr;
                b[0] = Bsm[n * GW + step * 8 + lc];
                b[1] = Bsm[n * GW + step * 8 + lc + 4];
                mma_fp16(acc[0][nf], a[0], b);
                mma_fp16(acc[1][nf], a[1], b);
            }
        }
        __syncthreads();
    }

    // epilogue: c0,c1 = row lr cols 2lc,2lc+1; c2,c3 = row lr+8
#pragma unroll
    for (int mf = 0; mf < 2; mf++)
#pragma unroll
        for (int nf = 0; nf < 8; nf++) {
            int r0i = m0 + wm + mf * 16 + lr;
            int col = n0 + wn + nf * 8 + 2 * lc;
            float v0 = acc[mf][nf][0], v1 = acc[mf][nf][1];
            float v2 = acc[mf][nf][2], v3 = acc[mf][nf][3];
            if (HAS_BIAS) {
                float b0 = bias[col], b1 = bias[col + 1];
                v0 += b0; v1 += b1; v2 += b0; v3 += b1;
            }
            if (sizeof(OutT) == 2) {
                __half2* p0 = (__half2*)((__half*)C + (size_t)r0i * N + col);
                __half2* p1 = (__half2*)((__half*)C + (size_t)(r0i + 8) * N + col);
                *p0 = __floats2half2_rn(v0, v1);
                *p1 = __floats2half2_rn(v2, v3);
            } else {
                float* c0p = (float*)C + (size_t)r0i * N + col;
                float* c1p = (float*)C + (size_t)(r0i + 8) * N + col;
                c0p[0] = v0; c0p[1] = v1;
                c1p[0] = v2; c1p[1] = v3;
            }
        }
}

// ---------------------------------------------------------------------------
// RoPE cos/sin table (fp64, fast-math-proof) + in-place apply on half qkv
// ---------------------------------------------------------------------------
__global__ void rope_table_kernel()
{
    int idx = blockIdx.x * blockDim.x + threadIdx.x;
    if (idx >= S_LEN * 64) return;
    int i = idx & 63;
    int s = idx >> 6;
    double invf_d = pow(10000.0, -(double)(2 * i) / 128.0);
    float invf_f  = (float)invf_d;
    float ang_f   = (float)s * invf_f;
    double ds, dc;
    sincos((double)ang_f, &ds, &dc);
    g_cos[idx] = (float)dc;
    g_sin[idx] = (float)ds;
}

__global__ void rope_apply_kernel(__half* __restrict__ qkv)
{
    int idx = blockIdx.x * blockDim.x + threadIdx.x;
    int j = idx & 63;
    int h = (idx >> 6) & 15;
    int s = idx >> 10;
    if (s >= S_LEN) return;

    float c  = g_cos[s * 64 + j];
    float sn = g_sin[s * 64 + j];

    __half* q = qkv + (size_t)s * QKV_N + h * HDIM + j;
    __half* k = q + HID;
    float q1 = __half2float(q[0]), q2 = __half2float(q[64]);
    q[0]  = __float2half(q1 * c - q2 * sn);
    q[64] = __float2half(q2 * c + q1 * sn);
    float k1 = __half2float(k[0]), k2 = __half2float(k[64]);
    k[0]  = __float2half(k1 * c - k2 * sn);
    k[64] = __float2half(k2 * c + k1 * sn);
}

// ---------------------------------------------------------------------------
// fp16 mma flash attention, causal. 128 queries x 1 head, 8 warps (16 rows).
// 32-key tiles. Q held as fp16 A-fragments (8 x k16 steps); scale applied
// post-mma in fp32. V stored transposed in smem for the PV row.col mma.
// Strides (words): K=68 (banks 4*key+lc), Vt=20 (banks 20*hd+lc),
// P=20 (banks 20*r+lc) — all full 32-bank permutations.
// ---------------------------------------------------------------------------
#define KW 68
#define VW 20
#define PW 20

__global__ __launch_bounds__(256) void flash_fp16_kernel(
    const __half* __restrict__ qkv, __half* __restrict__ ctx)
{
    __shared__ __align__(16) uint32_t Ks[32 * KW];        // 8704 B
    __shared__ __align__(16) uint32_t Vt[128 * VW];       // 10240 B
    __shared__ __align__(16) uint32_t Ps[8 * 16 * PW];    // 10240 B

    const int tid  = threadIdx.x;
    const int warp = tid >> 5;
    const int lane = tid & 31;
    const int lr = lane >> 2;
    const int lc = lane & 3;
    const int qt = 15 - blockIdx.x;        // heavy tiles first
    const int h  = blockIdx.y;
    const int q0 = qt * 128;
    const float scale = 0.08838834764831845f;  // 1/sqrt(128)

    // Q fragments: 8 k16 steps
    uint32_t qa[8][4];
    {
        const __half* Qb = qkv + (size_t)(q0 + warp * 16) * QKV_N + h * HDIM;
#pragma unroll
        for (int st = 0; st < 8; st++) {
            qa[st][0] = *(const uint32_t*)(Qb + (size_t)lr       * QKV_N + st * 16 + 2 * lc);
            qa[st][1] = *(const uint32_t*)(Qb + (size_t)(lr + 8) * QKV_N + st * 16 + 2 * lc);
            qa[st][2] = *(const uint32_t*)(Qb + (size_t)lr       * QKV_N + st * 16 + 2 * lc + 8);
            qa[st][3] = *(const uint32_t*)(Qb + (size_t)(lr + 8) * QKV_N + st * 16 + 2 * lc + 8);
        }
    }

    float o[16][4];
#pragma unroll
    for (int i = 0; i < 16; i++)
#pragma unroll
        for (int c = 0; c < 4; c++) o[i][c] = 0.f;
    float mA = -1e30f, mB = -1e30f, lA = 0.f, lB = 0.f;

    const int rowA = q0 + warp * 16 + lr;
    const int rowB = rowA + 8;
    const int rowMaxWarp = q0 + warp * 16 + 15;
    const int ntiles = qt * 4 + 4;

    for (int j = 0; j < ntiles; j++) {
        __syncthreads();
        // K tile (direct) + V tile (transposed) : 32 keys x 128 hd halves
#pragma unroll
        for (int it = 0; it < 2; it++) {
            int id  = tid + it * 256;          // 0..511
            int key = id >> 4;
            int ch  = id & 15;                  // 16B chunk = 8 halves
            const __half* Kg = qkv + (size_t)(j * 32 + key) * QKV_N + HID + h * HDIM + ch * 8;
            *(uint4*)&Ks[key * KW + ch * 4] = *(const uint4*)Kg;
            __half vh[8];
            *(uint4*)vh = *(const uint4*)(Kg + HID);
            int hd0 = ch * 8;
#pragma unroll
            for (int q = 0; q < 8; q++)
                ((__half*)Vt)[(hd0 + q) * (2 * VW) + key] = vh[q];
        }
        __syncthreads();

        const bool active = (j * 32 <= rowMaxWarp);
        float s[4][4];
        if (active) {
            // S = Q K^T (16 x 32 per warp)
#pragma unroll
            for (int nf = 0; nf < 4; nf++)
#pragma unroll
                for (int c = 0; c < 4; c++) s[nf][c] = 0.f;
#pragma unroll
            for (int st = 0; st < 8; st++) {
#pragma unroll
                for (int nf = 0; nf < 4; nf++) {
                    uint32_t b[2];
                    int key = nf * 8 + lr;
                    b[0] = Ks[key * KW + st * 8 + lc];
                    b[1] = Ks[key * KW + st * 8 + lc + 4];
                    mma_fp16(s[nf], qa[st], b);
                }
            }

            // scale (fp32, post-mma) + causal mask
#pragma unroll
            for (int nf = 0; nf < 4; nf++) {
                int col0 = j * 32 + nf * 8 + 2 * lc;
                s[nf][0] = (col0     > rowA) ? -1e30f : s[nf][0] * scale;
                s[nf][1] = (col0 + 1 > rowA) ? -1e30f : s[nf][1] * scale;
                s[nf][2] = (col0     > rowB) ? -1e30f : s[nf][2] * scale;
                s[nf][3] = (col0 + 1 > rowB) ? -1e30f : s[nf][3] * scale;
            }

            // online softmax
            float tA = -1e30f, tB = -1e30f;
#pragma unroll
            for (int nf = 0; nf < 4; nf++) {
                tA = fmaxf(tA, fmaxf(s[nf][0], s[nf][1]));
                tB = fmaxf(tB, fmaxf(s[nf][2], s[nf][3]));
            }
            tA = fmaxf(tA, __shfl_xor_sync(0xffffffffu, tA, 1));
            tA = fmaxf(tA, __shfl_xor_sync(0xffffffffu, tA, 2));
            tB = fmaxf(tB, __shfl_xor_sync(0xffffffffu, tB, 1));
            tB = fmaxf(tB, __shfl_xor_sync(0xffffffffu, tB, 2));

            float mAn = fmaxf(mA, tA), mBn = fmaxf(mB, tB);
            float aA = __expf(mA - mAn), aB = __expf(mB - mBn);
            float sA = 0.f, sB = 0.f;
#pragma unroll
            for (int nf = 0; nf < 4; nf++) {
                s[nf][0] = __expf(s[nf][0] - mAn);
                s[nf][1] = __expf(s[nf][1] - mAn);
                s[nf][2] = __expf(s[nf][2] - mBn);
                s[nf][3] = __expf(s[nf][3] - mBn);
                sA += s[nf][0] + s[nf][1];
                sB += s[nf][2] + s[nf][3];
            }
            sA += __shfl_xor_sync(0xffffffffu, sA, 1);
            sA += __shfl_xor_sync(0xffffffffu, sA, 2);
            sB += __shfl_xor_sync(0xffffffffu, sB, 1);
            sB += __shfl_xor_sync(0xffffffffu, sB, 2);
            lA = lA * aA + sA;
            lB = lB * aB + sB;
            mA = mAn; mB = mBn;
#pragma unroll
            for (int nf = 0; nf < 16; nf++) {
                o[nf][0] *= aA; o[nf][1] *= aA;
                o[nf][2] *= aB; o[nf][3] *= aB;
            }

            // P (half2-packed) -> per-warp smem
            uint32_t* P = Ps + warp * 16 * PW;
#pragma unroll
            for (int nf = 0; nf < 4; nf++) {
                P[lr       * PW + nf * 4 + lc] = pack_h2(s[nf][0], s[nf][1]);
                P[(lr + 8) * PW + nf * 4 + lc] = pack_h2(s[nf][2], s[nf][3]);
            }
            __syncwarp();

            // O += P V  (2 x k16 steps over 32 keys)
#pragma unroll
            for (int st = 0; st < 2; st++) {
                uint32_t pa[4];
                pa[0] = P[lr       * PW + st * 8 + lc];
                pa[1] = P[(lr + 8) * PW + st * 8 + lc];
                pa[2] = P[lr       * PW + st * 8 + lc + 4];
                pa[3] = P[(lr + 8) * PW + st * 8 + lc + 4];
#pragma unroll
                for (int nf = 0; nf < 16; nf++) {
                    uint32_t b[2];
                    int hd = nf * 8 + lr;
                    b[0] = Vt[hd * VW + st * 8 + lc];
                    b[1] = Vt[hd * VW + st * 8 + lc + 4];
                    mma_fp16(o[nf], pa, b);
                }
            }
        }
    }

    // epilogue: ctx half
    float rA = 1.f / lA, rB = 1.f / lB;
#pragma unroll
    for (int nf = 0; nf < 16; nf++) {
        int col = h * HDIM + nf * 8 + 2 * lc;
        *(__half2*)(ctx + (size_t)rowA * HID + col) =
            __floats2half2_rn(o[nf][0] * rA, o[nf][1] * rA);
        *(__half2*)(ctx + (size_t)rowB * HID + col) =
            __floats2half2_rn(o[nf][2] * rB, o[nf][3] * rB);
    }
}

// ---------------------------------------------------------------------------
// launcher
// ---------------------------------------------------------------------------
extern "C" void kernel_launch(void* const* d_in, const int* in_sizes, int n_in,
                              void* d_out, int out_size)
{
    const float* hidden = nullptr;
    const float* w_qkv  = nullptr;
    const float* b_qkv  = nullptr;
    const float* w_proj = nullptr;
    for (int i = 0; i < n_in; i++) {
        long sz = in_sizes[i];
        const float* p = (const float*)d_in[i];
        if (sz == (long)HID * QKV_N)      w_qkv = p;
        else if (sz == (long)QKV_N)       b_qkv = p;
        else {
            if (!hidden) hidden = p; else w_proj = p;
        }
    }
    float* out = (float*)d_out;

    __half *qkv_h, *ctx_h, *hid_h, *w1t, *w2t;
    cudaGetSymbolAddress((void**)&qkv_h, g_qkv_h);
    cudaGetSymbolAddress((void**)&ctx_h, g_ctx_h);
    cudaGetSymbolAddress((void**)&hid_h, g_hid_h);
    cudaGetSymbolAddress((void**)&w1t,   g_w1t_h);
    cudaGetSymbolAddress((void**)&w2t,   g_w2t_h);

    // 0) rope table + operand prep (half convert / transpose to [N,K])
    rope_table_kernel<<<(S_LEN * 64) / 256, 256>>>();
    convert_half_kernel<<<(S_LEN * HID / 4) / 256, 256>>>(hidden, hid_h, S_LEN * HID / 4);
    transpose_half_kernel<<<dim3(QKV_N / 32, HID / 32), dim3(32, 8)>>>(w_qkv, w1t, HID, QKV_N);
    transpose_half_kernel<<<dim3(HID / 32, HID / 32), dim3(32, 8)>>>(w_proj, w2t, HID, HID);

    // 1) qkv = hidden @ w_qkv + b  (fp16 mma, half output)
    gemm_fp16_kernel<true, __half><<<dim3(QKV_N / 128, S_LEN / 128), 256>>>(
        hid_h, w1t, b_qkv, qkv_h, S_LEN, QKV_N, HID);
    // 2) rope in-place on q,k (half)
    rope_apply_kernel<<<(S_LEN * NHEAD * 64) / 256, 256>>>(qkv_h);
    // 3) attention (fp16 mma flash)
    flash_fp16_kernel<<<dim3(S_LEN / 128, NHEAD), 256>>>(qkv_h, ctx_h);
    // 4) out = ctx @ w_proj  (fp16 mma, fp32 output)
    gemm_fp16_kernel<false, float><<<dim3(HID / 128, S_LEN / 128), 256>>>(
        ctx_h, w2t, nullptr, out, S_LEN, HID, HID);
}

// round 11
// speedup vs baseline: 4.2418x; 1.3592x over previous
#include <cuda_runtime.h>
#include <cuda_fp16.h>
#include <cstdint>

// ---------------------------------------------------------------------------
// QWenAttention: B=1, S=2048, H=2048, NH=16, HD=128
//   qkv = hidden @ w_qkv + b_qkv; rope(q,k); ctx = causal_attn(q,k,v);
//   out = ctx @ w_proj
// fp16 mma.sync m16n8k16 (fp32 accum) everywhere; ldmatrix fragment loads;
// cp.async pipelines (GEMM 2-stage, flash K/V 2-stage); fp64 RoPE table.
// ---------------------------------------------------------------------------

#define S_LEN 2048
#define HID   2048
#define NHEAD 16
#define HDIM  128
#define QKV_N 6144

__device__ __align__(16) __half g_qkv_h[S_LEN * QKV_N];
__device__ __align__(16) __half g_ctx_h[S_LEN * HID];
__device__ __align__(16) __half g_hid_h[S_LEN * HID];
__device__ __align__(16) __half g_w1t_h[QKV_N * HID];   // [N,K]
__device__ __align__(16) __half g_w2t_h[HID * HID];     // [N,K]
__device__ __align__(16) float  g_cos[S_LEN * 64];
__device__ __align__(16) float  g_sin[S_LEN * 64];

// ---------------------------------------------------------------------------
// helpers
// ---------------------------------------------------------------------------
__device__ __forceinline__ void mma_fp16(float* c, const uint32_t* a, const uint32_t* b) {
    asm volatile(
        "mma.sync.aligned.m16n8k16.row.col.f32.f16.f16.f32 "
        "{%0,%1,%2,%3}, {%4,%5,%6,%7}, {%8,%9}, {%0,%1,%2,%3};\n"
        : "+f"(c[0]), "+f"(c[1]), "+f"(c[2]), "+f"(c[3])
        : "r"(a[0]), "r"(a[1]), "r"(a[2]), "r"(a[3]), "r"(b[0]), "r"(b[1]));
}
__device__ __forceinline__ void ldsm_x4(uint32_t* r, uint32_t addr) {
    asm volatile("ldmatrix.sync.aligned.m8n8.x4.shared.b16 {%0,%1,%2,%3}, [%4];"
        : "=r"(r[0]), "=r"(r[1]), "=r"(r[2]), "=r"(r[3]) : "r"(addr));
}
__device__ __forceinline__ void ldsm_x4_t(uint32_t* r, uint32_t addr) {
    asm volatile("ldmatrix.sync.aligned.m8n8.x4.trans.shared.b16 {%0,%1,%2,%3}, [%4];"
        : "=r"(r[0]), "=r"(r[1]), "=r"(r[2]), "=r"(r[3]) : "r"(addr));
}
__device__ __forceinline__ void cpa16u(uint32_t s, const void* g) {
    asm volatile("cp.async.cg.shared.global [%0], [%1], 16;\n" :: "r"(s), "l"(g));
}
__device__ __forceinline__ uint32_t smem_u32(const void* p) {
    return (uint32_t)__cvta_generic_to_shared(p);
}
__device__ __forceinline__ uint32_t pack_h2(float lo, float hi) {
    __half2 h = __floats2half2_rn(lo, hi);
    return *(uint32_t*)&h;
}

// ---------------------------------------------------------------------------
// prep kernels
// ---------------------------------------------------------------------------
__global__ void convert_half_kernel(const float* __restrict__ in,
                                    __half* __restrict__ out, int n4)
{
    int i = blockIdx.x * blockDim.x + threadIdx.x;
    if (i >= n4) return;
    float4 v = ((const float4*)in)[i];
    ((__half2*)out)[i * 2]     = __floats2half2_rn(v.x, v.y);
    ((__half2*)out)[i * 2 + 1] = __floats2half2_rn(v.z, v.w);
}

__global__ void transpose_half_kernel(const float* __restrict__ in,
                                      __half* __restrict__ out, int R, int C)
{
    __shared__ float tile[32][33];
    int c0 = blockIdx.x * 32, r0 = blockIdx.y * 32;
    int tx = threadIdx.x, ty = threadIdx.y;
#pragma unroll
    for (int i = 0; i < 32; i += 8)
        tile[ty + i][tx] = in[(size_t)(r0 + ty + i) * C + c0 + tx];
    __syncthreads();
#pragma unroll
    for (int i = 0; i < 32; i += 8)
        out[(size_t)(c0 + ty + i) * R + r0 + tx] = __float2half(tile[tx][ty + i]);
}

__global__ void rope_table_kernel()
{
    int idx = blockIdx.x * blockDim.x + threadIdx.x;
    if (idx >= S_LEN * 64) return;
    int i = idx & 63;
    int s = idx >> 6;
    double invf_d = pow(10000.0, -(double)(2 * i) / 128.0);
    float invf_f  = (float)invf_d;
    float ang_f   = (float)s * invf_f;
    double ds, dc;
    sincos((double)ang_f, &ds, &dc);
    g_cos[idx] = (float)dc;
    g_sin[idx] = (float)ds;
}

__global__ void rope_apply_kernel(__half* __restrict__ qkv)
{
    int idx = blockIdx.x * blockDim.x + threadIdx.x;
    int j = idx & 63;
    int h = (idx >> 6) & 15;
    int s = idx >> 10;
    if (s >= S_LEN) return;
    float c  = g_cos[s * 64 + j];
    float sn = g_sin[s * 64 + j];
    __half* q = qkv + (size_t)s * QKV_N + h * HDIM + j;
    __half* k = q + HID;
    float q1 = __half2float(q[0]), q2 = __half2float(q[64]);
    q[0]  = __float2half(q1 * c - q2 * sn);
    q[64] = __float2half(q2 * c + q1 * sn);
    float k1 = __half2float(k[0]), k2 = __half2float(k[64]);
    k[0]  = __float2half(k1 * c - k2 * sn);
    k[64] = __float2half(k2 * c + k1 * sn);
}

// ---------------------------------------------------------------------------
// fp16 GEMM: C[M,N] = A[M,K] @ Bt^T (+bias); A [M,K], Bt [N,K] half.
// Block 128x128x32, 8 warps (4Mx2N), warp 32x64. ldmatrix fragments,
// cp.async 2-stage. Smem rows = 16 data words + 4 pad (stride 20).
// ---------------------------------------------------------------------------
#define GW 20

template <bool HAS_BIAS, typename OutT>
__global__ __launch_bounds__(256) void gemm_fp16_kernel(
    const __half* __restrict__ A, const __half* __restrict__ Bt,
    const float* __restrict__ bias, OutT* __restrict__ C,
    int M, int N, int K)
{
    __shared__ __align__(16) uint32_t As[2][128 * GW];
    __shared__ __align__(16) uint32_t Bs[2][128 * GW];

    const int tid  = threadIdx.x;
    const int warp = tid >> 5;
    const int lane = tid & 31;
    const int wm = (warp >> 1) * 32;
    const int wn = (warp & 1) * 64;
    const int m0 = blockIdx.y * 128;
    const int n0 = blockIdx.x * 128;

    // ldmatrix lane offsets
    const int l8  = lane & 7, sel = lane >> 3;
    const int a_row = l8 + ((sel & 1) << 3), a_col = (sel >> 1) << 2;  // A-type
    const int b_row = l8 + ((sel >> 1) << 3), b_col = (sel & 1) << 2;  // B-type

    float acc[2][8][4];
#pragma unroll
    for (int i = 0; i < 2; i++)
#pragma unroll
        for (int j = 0; j < 8; j++)
#pragma unroll
            for (int c = 0; c < 4; c++) acc[i][j][c] = 0.f;

    const int row = tid >> 1;
    const int jb  = (tid & 1) * 2;

    auto load_stage = [&](int st, int kb) {
#pragma unroll
        for (int j = 0; j < 2; j++) {
            int ch = jb + j;
            cpa16u(smem_u32(&As[st][row * GW + ch * 4]),
                   A + (size_t)(m0 + row) * K + kb + ch * 8);
            cpa16u(smem_u32(&Bs[st][row * GW + ch * 4]),
                   Bt + (size_t)(n0 + row) * K + kb + ch * 8);
        }
        asm volatile("cp.async.commit_group;\n" ::);
    };

    const int nk = K / 32;
    load_stage(0, 0);

    for (int t = 0; t < nk; t++) {
        if (t + 1 < nk) {
            load_stage((t + 1) & 1, (t + 1) * 32);
            asm volatile("cp.async.wait_group 1;\n" ::);
        } else {
            asm volatile("cp.async.wait_group 0;\n" ::);
        }
        __syncthreads();
        const uint32_t* Asm = As[t & 1];
        const uint32_t* Bsm = Bs[t & 1];

#pragma unroll
        for (int step = 0; step < 2; step++) {
            uint32_t a[2][4];
#pragma unroll
            for (int mf = 0; mf < 2; mf++)
                ldsm_x4(a[mf], smem_u32(&Asm[(wm + mf * 16 + a_row) * GW + step * 8 + a_col]));
#pragma unroll
            for (int nfp = 0; nfp < 4; nfp++) {
                uint32_t b[4];
                ldsm_x4(b, smem_u32(&Bsm[(wn + nfp * 16 + b_row) * GW + step * 8 + b_col]));
                mma_fp16(acc[0][2 * nfp],     a[0], b);
                mma_fp16(acc[1][2 * nfp],     a[1], b);
                mma_fp16(acc[0][2 * nfp + 1], a[0], b + 2);
                mma_fp16(acc[1][2 * nfp + 1], a[1], b + 2);
            }
        }
        __syncthreads();
    }

    const int lr = lane >> 2, lc = lane & 3;
#pragma unroll
    for (int mf = 0; mf < 2; mf++)
#pragma unroll
        for (int nf = 0; nf < 8; nf++) {
            int r0i = m0 + wm + mf * 16 + lr;
            int col = n0 + wn + nf * 8 + 2 * lc;
            float v0 = acc[mf][nf][0], v1 = acc[mf][nf][1];
            float v2 = acc[mf][nf][2], v3 = acc[mf][nf][3];
            if (HAS_BIAS) {
                float b0 = bias[col], b1 = bias[col + 1];
                v0 += b0; v1 += b1; v2 += b0; v3 += b1;
            }
            if (sizeof(OutT) == 2) {
                *(__half2*)((__half*)C + (size_t)r0i * N + col) = __floats2half2_rn(v0, v1);
                *(__half2*)((__half*)C + (size_t)(r0i + 8) * N + col) = __floats2half2_rn(v2, v3);
            } else {
                float* c0p = (float*)C + (size_t)r0i * N + col;
                float* c1p = (float*)C + (size_t)(r0i + 8) * N + col;
                c0p[0] = v0; c0p[1] = v1;
                c1p[0] = v2; c1p[1] = v3;
            }
        }
}

// ---------------------------------------------------------------------------
// fp16 flash attention, causal. 128 queries x 1 head, 8 warps (16 rows).
// 32-key tiles, cp.async double-buffered K/V, ldmatrix fragments
// (K: B-type; V: trans; P: A-type). Strides: K/V 68 words, P 20 words.
// ---------------------------------------------------------------------------
#define KW 68
#define PW 20

__global__ __launch_bounds__(256) void flash_fp16_kernel(
    const __half* __restrict__ qkv, __half* __restrict__ ctx)
{
    __shared__ __align__(16) uint32_t Ks[2][32 * KW];   // 8704 B each
    __shared__ __align__(16) uint32_t Vs[2][32 * KW];   // 8704 B each
    __shared__ __align__(16) uint32_t Ps[8 * 16 * PW];  // 10240 B

    const int tid  = threadIdx.x;
    const int warp = tid >> 5;
    const int lane = tid & 31;
    const int lr = lane >> 2;
    const int lc = lane & 3;
    const int qt = 15 - blockIdx.x;        // heavy tiles first
    const int h  = blockIdx.y;
    const int q0 = qt * 128;
    const float scale = 0.08838834764831845f;

    const int l8  = lane & 7, sel = lane >> 3;
    const int a_row = l8 + ((sel & 1) << 3), a_col = (sel >> 1) << 2;  // A/V-type
    const int b_row = l8 + ((sel >> 1) << 3), b_col = (sel & 1) << 2;  // B-type

    // Q fragments: 8 k16 steps (global, once)
    uint32_t qa[8][4];
    {
        const __half* Qb = qkv + (size_t)(q0 + warp * 16) * QKV_N + h * HDIM;
#pragma unroll
        for (int st = 0; st < 8; st++) {
            qa[st][0] = *(const uint32_t*)(Qb + (size_t)lr       * QKV_N + st * 16 + 2 * lc);
            qa[st][1] = *(const uint32_t*)(Qb + (size_t)(lr + 8) * QKV_N + st * 16 + 2 * lc);
            qa[st][2] = *(const uint32_t*)(Qb + (size_t)lr       * QKV_N + st * 16 + 2 * lc + 8);
            qa[st][3] = *(const uint32_t*)(Qb + (size_t)(lr + 8) * QKV_N + st * 16 + 2 * lc + 8);
        }
    }

    float o[16][4];
#pragma unroll
    for (int i = 0; i < 16; i++)
#pragma unroll
        for (int c = 0; c < 4; c++) o[i][c] = 0.f;
    float mA = -1e30f, mB = -1e30f, lA = 0.f, lB = 0.f;

    const int rowA = q0 + warp * 16 + lr;
    const int rowB = rowA + 8;
    const int rowMaxWarp = q0 + warp * 16 + 15;
    const int ntiles = qt * 4 + 4;

    auto load_tile = [&](int st, int jt) {
#pragma unroll
        for (int it = 0; it < 2; it++) {
            int id  = tid + it * 256;       // 0..511
            int key = id >> 4;
            int ch  = id & 15;
            const __half* Kg = qkv + (size_t)(jt * 32 + key) * QKV_N + HID + h * HDIM + ch * 8;
            cpa16u(smem_u32(&Ks[st][key * KW + ch * 4]), Kg);
            cpa16u(smem_u32(&Vs[st][key * KW + ch * 4]), Kg + HID);
        }
        asm volatile("cp.async.commit_group;\n" ::);
    };

    load_tile(0, 0);

    for (int j = 0; j < ntiles; j++) {
        asm volatile("cp.async.wait_group 0;\n" ::);
        __syncthreads();
        if (j + 1 < ntiles) load_tile((j + 1) & 1, j + 1);

        const uint32_t* Ksm = Ks[j & 1];
        const uint32_t* Vsm = Vs[j & 1];
        const bool active = (j * 32 <= rowMaxWarp);
        if (active) {
            // S = Q K^T (16 x 32 per warp)
            float s[4][4];
#pragma unroll
            for (int nf = 0; nf < 4; nf++)
#pragma unroll
                for (int c = 0; c < 4; c++) s[nf][c] = 0.f;
#pragma unroll
            for (int st = 0; st < 8; st++) {
#pragma unroll
                for (int nfp = 0; nfp < 2; nfp++) {
                    uint32_t b[4];
                    ldsm_x4(b, smem_u32(&Ksm[(nfp * 16 + b_row) * KW + st * 8 + b_col]));
                    mma_fp16(s[2 * nfp],     qa[st], b);
                    mma_fp16(s[2 * nfp + 1], qa[st], b + 2);
                }
            }

            // scale + causal mask
#pragma unroll
            for (int nf = 0; nf < 4; nf++) {
                int col0 = j * 32 + nf * 8 + 2 * lc;
                s[nf][0] = (col0     > rowA) ? -1e30f : s[nf][0] * scale;
                s[nf][1] = (col0 + 1 > rowA) ? -1e30f : s[nf][1] * scale;
                s[nf][2] = (col0     > rowB) ? -1e30f : s[nf][2] * scale;
                s[nf][3] = (col0 + 1 > rowB) ? -1e30f : s[nf][3] * scale;
            }

            // online softmax
            float tA = -1e30f, tB = -1e30f;
#pragma unroll
            for (int nf = 0; nf < 4; nf++) {
                tA = fmaxf(tA, fmaxf(s[nf][0], s[nf][1]));
                tB = fmaxf(tB, fmaxf(s[nf][2], s[nf][3]));
            }
            tA = fmaxf(tA, __shfl_xor_sync(0xffffffffu, tA, 1));
            tA = fmaxf(tA, __shfl_xor_sync(0xffffffffu, tA, 2));
            tB = fmaxf(tB, __shfl_xor_sync(0xffffffffu, tB, 1));
            tB = fmaxf(tB, __shfl_xor_sync(0xffffffffu, tB, 2));

            float mAn = fmaxf(mA, tA), mBn = fmaxf(mB, tB);
            float aA = __expf(mA - mAn), aB = __expf(mB - mBn);
            float sA = 0.f, sB = 0.f;
#pragma unroll
            for (int nf = 0; nf < 4; nf++) {
                s[nf][0] = __expf(s[nf][0] - mAn);
                s[nf][1] = __expf(s[nf][1] - mAn);
                s[nf][2] = __expf(s[nf][2] - mBn);
                s[nf][3] = __expf(s[nf][3] - mBn);
                sA += s[nf][0] + s[nf][1];
                sB += s[nf][2] + s[nf][3];
            }
            sA += __shfl_xor_sync(0xffffffffu, sA, 1);
            sA += __shfl_xor_sync(0xffffffffu, sA, 2);
            sB += __shfl_xor_sync(0xffffffffu, sB, 1);
            sB += __shfl_xor_sync(0xffffffffu, sB, 2);
            lA = lA * aA + sA;
            lB = lB * aB + sB;
            mA = mAn; mB = mBn;
#pragma unroll
            for (int nf = 0; nf < 16; nf++) {
                o[nf][0] *= aA; o[nf][1] *= aA;
                o[nf][2] *= aB; o[nf][3] *= aB;
            }

            // P (half2) -> per-warp smem
            uint32_t* P = Ps + warp * 16 * PW;
#pragma unroll
            for (int nf = 0; nf < 4; nf++) {
                P[lr       * PW + nf * 4 + lc] = pack_h2(s[nf][0], s[nf][1]);
                P[(lr + 8) * PW + nf * 4 + lc] = pack_h2(s[nf][2], s[nf][3]);
            }
            __syncwarp();

            // O += P V  (V fragment via ldmatrix.trans on [key][hd] tile)
#pragma unroll
            for (int st = 0; st < 2; st++) {
                uint32_t pa[4];
                ldsm_x4(pa, smem_u32(&P[a_row * PW + st * 8 + a_col]));
#pragma unroll
                for (int nfp = 0; nfp < 8; nfp++) {
                    uint32_t b[4];
                    ldsm_x4_t(b, smem_u32(&Vsm[(st * 16 + a_row) * KW + nfp * 8 + a_col]));
                    mma_fp16(o[2 * nfp],     pa, b);
                    mma_fp16(o[2 * nfp + 1], pa, b + 2);
                }
            }
        }
    }

    float rA = 1.f / lA, rB = 1.f / lB;
#pragma unroll
    for (int nf = 0; nf < 16; nf++) {
        int col = h * HDIM + nf * 8 + 2 * lc;
        *(__half2*)(ctx + (size_t)rowA * HID + col) =
            __floats2half2_rn(o[nf][0] * rA, o[nf][1] * rA);
        *(__half2*)(ctx + (size_t)rowB * HID + col) =
            __floats2half2_rn(o[nf][2] * rB, o[nf][3] * rB);
    }
}

// ---------------------------------------------------------------------------
// launcher
// ---------------------------------------------------------------------------
extern "C" void kernel_launch(void* const* d_in, const int* in_sizes, int n_in,
                              void* d_out, int out_size)
{
    const float* hidden = nullptr;
    const float* w_qkv  = nullptr;
    const float* b_qkv  = nullptr;
    const float* w_proj = nullptr;
    for (int i = 0; i < n_in; i++) {
        long sz = in_sizes[i];
        const float* p = (const float*)d_in[i];
        if (sz == (long)HID * QKV_N)      w_qkv = p;
        else if (sz == (long)QKV_N)       b_qkv = p;
        else {
            if (!hidden) hidden = p; else w_proj = p;
        }
    }
    float* out = (float*)d_out;

    __half *qkv_h, *ctx_h, *hid_h, *w1t, *w2t;
    cudaGetSymbolAddress((void**)&qkv_h, g_qkv_h);
    cudaGetSymbolAddress((void**)&ctx_h, g_ctx_h);
    cudaGetSymbolAddress((void**)&hid_h, g_hid_h);
    cudaGetSymbolAddress((void**)&w1t,   g_w1t_h);
    cudaGetSymbolAddress((void**)&w2t,   g_w2t_h);

    rope_table_kernel<<<(S_LEN * 64) / 256, 256>>>();
    convert_half_kernel<<<(S_LEN * HID / 4) / 256, 256>>>(hidden, hid_h, S_LEN * HID / 4);
    transpose_half_kernel<<<dim3(QKV_N / 32, HID / 32), dim3(32, 8)>>>(w_qkv, w1t, HID, QKV_N);
    transpose_half_kernel<<<dim3(HID / 32, HID / 32), dim3(32, 8)>>>(w_proj, w2t, HID, HID);

    gemm_fp16_kernel<true, __half><<<dim3(QKV_N / 128, S_LEN / 128), 256>>>(
        hid_h, w1t, b_qkv, qkv_h, S_LEN, QKV_N, HID);
    rope_apply_kernel<<<(S_LEN * NHEAD * 64) / 256, 256>>>(qkv_h);
    flash_fp16_kernel<<<dim3(S_LEN / 128, NHEAD), 256>>>(qkv_h, ctx_h);
    gemm_fp16_kernel<false, float><<<dim3(HID / 128, S_LEN / 128), 256>>>(
        ctx_h, w2t, nullptr, out, S_LEN, HID, HID);
}